// round 12
// baseline (speedup 1.0000x reference)
#include <cuda_runtime.h>
#include <cstdint>

#define NSTEPS   730
#define NGRID    8000
#define HALF     4000        // thread owns cells g and g+HALF
#define UHL      15
#define CH       10          // timesteps per smem chunk; 730 = 73 * 10
#define BT       32          // one warp per block, warp-private staging
#define NCHUNK   (NSTEPS / CH)
#define PIPE     4           // cp.async pipeline depth
#define NEARZERO 1e-5f

__device__ __forceinline__ float ex2_(float x) {
    float r; asm("ex2.approx.ftz.f32 %0, %1;" : "=f"(r) : "f"(x)); return r;
}
__device__ __forceinline__ float lg2_(float x) {
    float r; asm("lg2.approx.ftz.f32 %0, %1;" : "=f"(r) : "f"(x)); return r;
}
__device__ __forceinline__ float sigmoidf_(float x) {
    return 1.0f / (1.0f + __expf(-x));
}

__device__ __forceinline__ uint32_t smem_u32(const void* p) {
    uint32_t a;
    asm("{ .reg .u64 t; cvta.to.shared.u64 t, %1; cvt.u32.u64 %0, t; }" : "=r"(a) : "l"(p));
    return a;
}
__device__ __forceinline__ void cp_async16(uint32_t dst, const void* src) {
    asm volatile("cp.async.ca.shared.global [%0], [%1], 16;\n" :: "r"(dst), "l"(src));
}
__device__ __forceinline__ void cp_commit() { asm volatile("cp.async.commit_group;\n"); }
__device__ __forceinline__ void cp_wait3() { asm volatile("cp.async.wait_group 3;\n"); }

// smem staging: [PIPE][2 cell-groups][CH steps][BT*3 floats] = 30 KB
__shared__ float sbuf[PIPE][2][CH][BT * 3];

__device__ __forceinline__ void issue_chunk(const float* __restrict__ xphy,
                                            int c, int pb, int g0, int tid,
                                            uint32_t sbase) {
    const int t0 = c * CH;
    constexpr int ROW16 = BT * 3 / 4;          // 24 16B units per (group,row)
    constexpr int TOT16 = 2 * CH * ROW16;      // 480
    #pragma unroll 1
    for (int idx = tid; idx < TOT16; idx += BT) {
        int grp = idx / (CH * ROW16);
        int rem = idx - grp * (CH * ROW16);
        int row = rem / ROW16;
        int col = rem - row * ROW16;
        const float* src = xphy
            + ((size_t)(t0 + row) * NGRID + (size_t)(g0 + grp * HALF)) * 3 + col * 4;
        uint32_t dst = sbase
            + (uint32_t)((((pb * 2 + grp) * CH + row) * (BT * 3) + col * 4) * 4);
        cp_async16(dst, src);
    }
    cp_commit();
}

__global__ __launch_bounds__(BT, 1)
void hbv_kernel(const float* __restrict__ xphy,    // [T, G, 3]
                const float* __restrict__ params,  // [T, G, 16]
                float*       __restrict__ out)     // [T, G, 4]
{
    const int tid = threadIdx.x;
    const int g0  = blockIdx.x * BT;
    const uint32_t sbase = smem_u32(&sbuf[0][0][0][0]);

    int gi[2];
    gi[0] = g0 + tid;
    gi[1] = g0 + tid + HALF;

    // ---------------- per-cell parameters ----------------
    float pBETA[2], pFC[2], invfc[2], pK0[2], pK1[2], pK2[2];
    float pPERC[2], pUZL[2], pTT[2], pCFMAX[2], cfrcf[2], pCWH[2], pBETAET[2], pC[2];
    float nBlg2FC[2], nBElg2LP[2];
    float w[2][UHL];

    #pragma unroll
    for (int c = 0; c < 2; c++) {
        const float* pr = params + ((size_t)(NSTEPS - 1) * NGRID + (size_t)gi[c]) * 16;
        float4 r0 = *(const float4*)(pr + 0);
        float4 r1 = *(const float4*)(pr + 4);
        float4 r2 = *(const float4*)(pr + 8);
        float4 r3 = *(const float4*)(pr + 12);

        pBETA[c]   = 1.0f   + sigmoidf_(r0.x) * 5.0f;
        pFC[c]     = 50.0f  + sigmoidf_(r0.y) * 950.0f;
        pK0[c]     = 0.05f  + sigmoidf_(r0.z) * 0.85f;
        pK1[c]     = 0.01f  + sigmoidf_(r0.w) * 0.49f;
        pK2[c]     = 0.001f + sigmoidf_(r1.x) * 0.199f;
        float pLP  = 0.2f   + sigmoidf_(r1.y) * 0.8f;
        pPERC[c]   =          sigmoidf_(r1.z) * 10.0f;
        pUZL[c]    =          sigmoidf_(r1.w) * 100.0f;
        pTT[c]     = -2.5f  + sigmoidf_(r2.x) * 5.0f;
        pCFMAX[c]  = 0.5f   + sigmoidf_(r2.y) * 9.5f;
        cfrcf[c]   =          sigmoidf_(r2.z) * 0.1f * pCFMAX[c];
        pCWH[c]    =          sigmoidf_(r2.w) * 0.2f;
        pBETAET[c] = 0.3f   + sigmoidf_(r3.x) * 4.7f;
        pC[c]      =          sigmoidf_(r3.y);
        float route_a =       sigmoidf_(r3.z) * 2.9f;
        float route_b =       sigmoidf_(r3.w) * 6.5f;

        invfc[c]    = __fdividef(1.0f, pFC[c]);
        // pow folding: (x/s)^b = ex2(b*lg2(x) - b*lg2(s))
        nBlg2FC[c]  = -pBETA[c]   * lg2_(pFC[c]);
        nBElg2LP[c] = -pBETAET[c] * lg2_(pLP * pFC[c]);

        // gamma UH weights; Gamma(a)*theta^a cancels in normalization
        const float aa    = fmaxf(route_a, 0.0f) + 0.1f;
        const float theta = fmaxf(route_b, 0.0f) + 0.5f;
        const float am1   = aa - 1.0f;
        const float invth = __fdividef(1.0f, theta);
        float wsum = 0.0f;
        #pragma unroll
        for (int k = 0; k < UHL; k++) {
            float tk = (float)k + 0.5f;
            float v  = __expf(am1 * __logf(tk) - tk * invth);
            w[c][k] = v;
            wsum += v;
        }
        const float inv_wsum = __fdividef(1.0f, wsum);
        #pragma unroll
        for (int k = 0; k < UHL; k++) w[c][k] *= inv_wsum;
    }

    // ---------------- state ----------------
    float SNOWPACK[2], MELTWATER[2], SM[2], SUZ[2], SLZ[2], sw[2];
    float pQ0[2], pQ1[2], pQ2[2];
    float a0[2][UHL - 1], a1[2][UHL - 1], a2[2][UHL - 1];
    #pragma unroll
    for (int c = 0; c < 2; c++) {
        SNOWPACK[c] = 0.001f; MELTWATER[c] = 0.001f;
        SM[c] = 0.001f; SUZ[c] = 0.001f; SLZ[c] = 0.001f;
        sw[c] = fminf(ex2_(fmaf(pBETA[c], lg2_(SM[c]), nBlg2FC[c])), 1.0f);
        pQ0[c] = 0.0f; pQ1[c] = 0.0f; pQ2[c] = 0.0f;
        #pragma unroll
        for (int j = 0; j < UHL - 1; j++) { a0[c][j] = 0.0f; a1[c][j] = 0.0f; a2[c][j] = 0.0f; }
    }

    // prologue: fill 4-deep pipeline
    issue_chunk(xphy, 0, 0, g0, tid, sbase);
    issue_chunk(xphy, 1, 1, g0, tid, sbase);
    issue_chunk(xphy, 2, 2, g0, tid, sbase);
    issue_chunk(xphy, 3, 3, g0, tid, sbase);

    float4* __restrict__ out4 = (float4*)out;
    const int s3 = tid * 3;

    for (int k = 0; k < NCHUNK; k++) {
        const int pb = k & (PIPE - 1);
        cp_wait3();
        __syncwarp();

        #pragma unroll
        for (int u = 0; u < CH; u++) {
            const int t = k * CH + u;

            #pragma unroll
            for (int c = 0; c < 2; c++) {
                const float P   = sbuf[pb][c][u][s3 + 0];
                const float Tt  = sbuf[pb][c][u][s3 + 1];
                const float PET = sbuf[pb][c][u][s3 + 2];

                // ---- snow chain ----
                const float RAIN = (Tt >= pTT[c]) ? P : 0.0f;
                const float SNOW = (Tt <  pTT[c]) ? P : 0.0f;
                float sp = SNOWPACK[c] + SNOW;
                const float melt = fminf(fmaxf(pCFMAX[c] * (Tt - pTT[c]), 0.0f), sp);
                float mw = MELTWATER[c] + melt;
                sp -= melt;
                const float refreeze = fminf(fmaxf(cfrcf[c] * (pTT[c] - Tt), 0.0f), mw);
                sp += refreeze;
                mw -= refreeze;
                const float tosoil = fmaxf(mw - pCWH[c] * sp, 0.0f);
                MELTWATER[c] = mw - tosoil;
                SNOWPACK[c]  = sp;

                // ---- soil moisture (sw carried from previous iteration) ----
                const float rt   = RAIN + tosoil;
                const float smrt = SM[c] + rt;
                const float recharge = rt * sw[c];
                const float SM1 = fmaf(-rt, sw[c], smrt);
                const float excess = fmaxf(SM1 - pFC[c], 0.0f);
                const float SM2 = fminf(SM1, pFC[c]);
                // capillary (min-with-SLZ redundant: C<=1, SM2<=FC)
                const float cSLZ = pC[c] * SLZ[c];
                const float cap  = cSLZ * fmaf(-invfc[c], SM2, 1.0f);
                const float SM3  = fmaxf(SM2 + cap, NEARZERO);
                const float SLZa = fmaxf(SLZ[c] - cap, NEARZERO);

                // ---- launch evapfactor pow ----
                const float ef_raw = ex2_(fmaf(pBETAET[c], lg2_(SM3), nBElg2LP[c]));

                // ==== FILL the pow latency: conv + store of PREVIOUS step ====
                {
                    const float q0 = pQ0[c], q1 = pQ1[c], q2 = pQ2[c];
                    const float y0 = a0[c][0] + w[c][0] * q0;
                    const float y1 = a1[c][0] + w[c][0] * q1;
                    const float y2 = a2[c][0] + w[c][0] * q2;
                    #pragma unroll
                    for (int j = 0; j < UHL - 2; j++) {
                        a0[c][j] = a0[c][j + 1] + w[c][j + 1] * q0;
                        a1[c][j] = a1[c][j + 1] + w[c][j + 1] * q1;
                        a2[c][j] = a2[c][j + 1] + w[c][j + 1] * q2;
                    }
                    a0[c][UHL - 2] = w[c][UHL - 1] * q0;
                    a1[c][UHL - 2] = w[c][UHL - 1] * q1;
                    a2[c][UHL - 2] = w[c][UHL - 1] * q2;
                    if (t > 0) {
                        float4 o;
                        o.x = y0 + y1 + y2;
                        o.y = y0;
                        o.z = y1;
                        o.w = y2;
                        out4[(size_t)(t - 1) * NGRID + gi[c]] = o;
                    }
                }

                // ---- ET and SM update ----
                const float ef = fminf(ef_raw, 1.0f);
                const float ET = fminf(PET * ef, SM3);
                SM[c] = fmaxf(SM3 - ET, NEARZERO);

                // ---- launch next step's soil-wetness pow ----
                sw[c] = fminf(ex2_(fmaf(pBETA[c], lg2_(SM[c]), nBlg2FC[c])), 1.0f);

                // ==== FILL: response routine (independent of sw) ====
                float suz = SUZ[c] + recharge + excess;
                const float perc = fminf(suz, pPERC[c]);
                suz -= perc;
                const float Q0 = pK0[c] * fmaxf(suz - pUZL[c], 0.0f);
                suz -= Q0;
                const float Q1 = pK1[c] * suz;
                SUZ[c] = suz - Q1;
                float slz = SLZa + perc;
                const float Q2 = pK2[c] * slz;
                SLZ[c] = slz - Q2;

                pQ0[c] = Q0; pQ1[c] = Q1; pQ2[c] = Q2;
            }
        }

        __syncwarp();
        if (k + PIPE < NCHUNK)
            issue_chunk(xphy, k + PIPE, pb, g0, tid, sbase);
        else
            cp_commit();
    }

    // epilogue: conv + store of the final step (both cells)
    #pragma unroll
    for (int c = 0; c < 2; c++) {
        const float y0 = a0[c][0] + w[c][0] * pQ0[c];
        const float y1 = a1[c][0] + w[c][0] * pQ1[c];
        const float y2 = a2[c][0] + w[c][0] * pQ2[c];
        float4 o;
        o.x = y0 + y1 + y2;
        o.y = y0;
        o.z = y1;
        o.w = y2;
        out4[(size_t)(NSTEPS - 1) * NGRID + gi[c]] = o;
    }
}

extern "C" void kernel_launch(void* const* d_in, const int* in_sizes, int n_in,
                              void* d_out, int out_size) {
    const float* xphy   = (const float*)d_in[0];   // [730, 8000, 3]
    const float* params = (const float*)d_in[1];   // [730, 8000, 16]
    float* out = (float*)d_out;                    // [730, 8000, 4]
    (void)in_sizes; (void)n_in; (void)out_size;

    dim3 block(BT);
    dim3 grid(HALF / BT);   // 125 warp-private blocks, 2 cells per thread
    hbv_kernel<<<grid, block>>>(xphy, params, out);
}

// round 13
// speedup vs baseline: 2.4009x; 2.4009x over previous
#include <cuda_runtime.h>
#include <cstdint>

#define NSTEPS   730
#define NGRID    8000
#define UHL      15
#define CH       10          // timesteps per smem chunk; 730 = 73 * 10
#define BT       32          // one warp per block, warp-private staging
#define NCHUNK   (NSTEPS / CH)
#define PIPE     4           // cp.async pipeline depth
#define NEARZERO 1e-5f

typedef unsigned long long u64;

__device__ __forceinline__ float ex2_(float x) {
    float r; asm("ex2.approx.ftz.f32 %0, %1;" : "=f"(r) : "f"(x)); return r;
}
__device__ __forceinline__ float lg2_(float x) {
    float r; asm("lg2.approx.ftz.f32 %0, %1;" : "=f"(r) : "f"(x)); return r;
}
__device__ __forceinline__ float sigmoidf_(float x) {
    return 1.0f / (1.0f + __expf(-x));
}

// ---- packed f32x2 (Blackwell FFMA2 path, PTX-only) ----
__device__ __forceinline__ u64 pack2(float lo, float hi) {
    u64 r; asm("mov.b64 %0,{%1,%2};" : "=l"(r) : "f"(lo), "f"(hi)); return r;
}
__device__ __forceinline__ void unpack2(u64 v, float& lo, float& hi) {
    asm("mov.b64 {%0,%1},%2;" : "=f"(lo), "=f"(hi) : "l"(v));
}
__device__ __forceinline__ u64 fma2(u64 a, u64 b, u64 c) {
    u64 d; asm("fma.rn.f32x2 %0,%1,%2,%3;" : "=l"(d) : "l"(a), "l"(b), "l"(c)); return d;
}
__device__ __forceinline__ u64 mul2(u64 a, u64 b) {
    u64 d; asm("mul.rn.f32x2 %0,%1,%2;" : "=l"(d) : "l"(a), "l"(b)); return d;
}

__device__ __forceinline__ uint32_t smem_u32(const void* p) {
    uint32_t a;
    asm("{ .reg .u64 t; cvta.to.shared.u64 t, %1; cvt.u32.u64 %0, t; }" : "=r"(a) : "l"(p));
    return a;
}
__device__ __forceinline__ void cp_async16(uint32_t dst, const void* src) {
    asm volatile("cp.async.ca.shared.global [%0], [%1], 16;\n" :: "r"(dst), "l"(src));
}
__device__ __forceinline__ void cp_commit() { asm volatile("cp.async.commit_group;\n"); }
__device__ __forceinline__ void cp_wait3() { asm volatile("cp.async.wait_group 3;\n"); }

// smem staging: [PIPE buffers][CH steps][BT*3 floats]   (one warp per block)
__shared__ float sbuf[PIPE][CH][BT * 3];

__device__ __forceinline__ void issue_chunk(const float* __restrict__ xphy,
                                            int c, int pb, int g0, int tid,
                                            uint32_t sbase) {
    const int t0 = c * CH;
    constexpr int ROW16 = BT * 3 / 4;        // 24 16B units per row
    constexpr int TOT16 = CH * ROW16;        // 240
    #pragma unroll 1
    for (int idx = tid; idx < TOT16; idx += BT) {
        int row = idx / ROW16;
        int col = idx - row * ROW16;
        const float* src = xphy + ((size_t)(t0 + row) * NGRID + (size_t)g0) * 3 + col * 4;
        uint32_t dst = sbase + (uint32_t)(((pb * CH + row) * (BT * 3) + col * 4) * 4);
        cp_async16(dst, src);
    }
    cp_commit();
}

__global__ __launch_bounds__(BT, 1)
void hbv_kernel(const float* __restrict__ xphy,    // [T, G, 3]
                const float* __restrict__ params,  // [T, G, 16]
                float*       __restrict__ out)     // [T, G, 4]
{
    const int tid = threadIdx.x;
    const int g0  = blockIdx.x * BT;
    const int g   = g0 + tid;
    const uint32_t sbase = smem_u32(&sbuf[0][0][0]);

    // ---------------- static parameters (last timestep only) ----------------
    const float* pr = params + ((size_t)(NSTEPS - 1) * NGRID + (size_t)g) * 16;
    float4 r0 = *(const float4*)(pr + 0);
    float4 r1 = *(const float4*)(pr + 4);
    float4 r2 = *(const float4*)(pr + 8);
    float4 r3 = *(const float4*)(pr + 12);

    const float parBETA   = 1.0f   + sigmoidf_(r0.x) * 5.0f;
    const float parFC     = 50.0f  + sigmoidf_(r0.y) * 950.0f;
    const float parK0     = 0.05f  + sigmoidf_(r0.z) * 0.85f;
    const float parK1     = 0.01f  + sigmoidf_(r0.w) * 0.49f;
    const float parK2     = 0.001f + sigmoidf_(r1.x) * 0.199f;
    const float parLP     = 0.2f   + sigmoidf_(r1.y) * 0.8f;
    const float parPERC   =          sigmoidf_(r1.z) * 10.0f;
    const float parUZL    =          sigmoidf_(r1.w) * 100.0f;
    const float parTT     = -2.5f  + sigmoidf_(r2.x) * 5.0f;
    const float parCFMAX  = 0.5f   + sigmoidf_(r2.y) * 9.5f;
    const float cfr_cfmax =          sigmoidf_(r2.z) * 0.1f * parCFMAX;
    const float parCWH    =          sigmoidf_(r2.w) * 0.2f;
    const float parBETAET = 0.3f   + sigmoidf_(r3.x) * 4.7f;
    const float parC      =          sigmoidf_(r3.y);
    const float route_a   =          sigmoidf_(r3.z) * 2.9f;
    const float route_b   =          sigmoidf_(r3.w) * 6.5f;

    const float inv_fc   = __fdividef(1.0f, parFC);
    // pow folding: (x/s)^b = ex2(b*lg2(x) - b*lg2(s))
    const float nBlg2FC  = -parBETA   * lg2_(parFC);
    const float nBElg2LP = -parBETAET * lg2_(parLP * parFC);
    // FMA-folded constants
    const float cfmaxTT  = parCFMAX  * parTT;   // melt    = max(CFMAX*Tt - cfmaxTT, 0)
    const float cfrcfTT  = cfr_cfmax * parTT;   // refreeze= max(cfrcfTT - cfrcf*Tt, 0)
    const float k0uzl    = parK0     * parUZL;  // Q0      = max(K0*suz - k0uzl, 0)

    // gamma UH weights; Gamma(a)*theta^a cancels in normalization
    const float aa    = fmaxf(route_a, 0.0f) + 0.1f;
    const float theta = fmaxf(route_b, 0.0f) + 0.5f;
    const float am1   = aa - 1.0f;
    const float invth = __fdividef(1.0f, theta);

    float w[UHL];
    float wsum = 0.0f;
    #pragma unroll
    for (int k = 0; k < UHL; k++) {
        float tk = (float)k + 0.5f;
        float v  = __expf(am1 * __logf(tk) - tk * invth);
        w[k] = v;
        wsum += v;
    }
    const float inv_wsum = __fdividef(1.0f, wsum);
    #pragma unroll
    for (int k = 0; k < UHL; k++) w[k] *= inv_wsum;

    // packed weights (w, w) for the series-0/1 packed convolution
    u64 wp[UHL];
    #pragma unroll
    for (int k = 0; k < UHL; k++) wp[k] = pack2(w[k], w[k]);

    // ---------------- state ----------------
    float SNOWPACK = 0.001f, MELTWATER = 0.001f, SM = 0.001f, SUZ = 0.001f, SLZ = 0.001f;
    // conv accumulators: series 0&1 packed, series 2 scalar
    u64   A01[UHL - 1];
    float a2[UHL - 1];
    #pragma unroll
    for (int j = 0; j < UHL - 1; j++) { A01[j] = 0ULL; a2[j] = 0.0f; }

    // software-pipeline carries: sw for the upcoming step, Qs of previous step
    float sw = fminf(ex2_(fmaf(parBETA, lg2_(SM), nBlg2FC)), 1.0f);
    float pQ0 = 0.0f, pQ1 = 0.0f, pQ2 = 0.0f;   // fictitious step -1 (zeros: exact)

    // prologue: fill 4-deep pipeline
    issue_chunk(xphy, 0, 0, g0, tid, sbase);
    issue_chunk(xphy, 1, 1, g0, tid, sbase);
    issue_chunk(xphy, 2, 2, g0, tid, sbase);
    issue_chunk(xphy, 3, 3, g0, tid, sbase);

    float4* __restrict__ out4 = (float4*)out;
    const int s3 = tid * 3;

    for (int k = 0; k < NCHUNK; k++) {
        const int pb = k & (PIPE - 1);
        cp_wait3();            // chunk k complete (<=3 newer groups in flight)
        __syncwarp();          // publish other lanes' copies within the warp

        #pragma unroll
        for (int u = 0; u < CH; u++) {
            const int t = k * CH + u;
            const float P   = sbuf[pb][u][s3 + 0];
            const float Tt  = sbuf[pb][u][s3 + 1];
            const float PET = sbuf[pb][u][s3 + 2];

            // ---- snow chain (FMA-folded) ----
            const float RAIN = (Tt >= parTT) ? P : 0.0f;
            const float SNOW = (Tt <  parTT) ? P : 0.0f;
            float sp = SNOWPACK + SNOW;
            const float melt = fminf(fmaxf(fmaf(parCFMAX, Tt, -cfmaxTT), 0.0f), sp);
            float mw = MELTWATER + melt;
            sp -= melt;
            const float refreeze = fminf(fmaxf(fmaf(-cfr_cfmax, Tt, cfrcfTT), 0.0f), mw);
            sp += refreeze;
            mw -= refreeze;
            const float tosoil = fmaxf(fmaf(-parCWH, sp, mw), 0.0f);
            MELTWATER = mw - tosoil;
            SNOWPACK  = sp;

            // ---- soil moisture (sw precomputed last iteration) ----
            const float rt   = RAIN + tosoil;
            const float smrt = SM + rt;
            const float recharge = rt * sw;
            const float SM1 = fmaf(-rt, sw, smrt);
            const float excess = fmaxf(SM1 - parFC, 0.0f);
            const float SM2 = fminf(SM1, parFC);
            // capillary (min-with-SLZ redundant: C<=1 and SM2<=FC)
            const float cSLZ = parC * SLZ;
            const float cap  = cSLZ * fmaf(-inv_fc, SM2, 1.0f);
            const float SM3  = fmaxf(SM2 + cap, NEARZERO);
            const float SLZa = fmaxf(SLZ - cap, NEARZERO);

            // ---- launch evapfactor pow: min((SM3/(LP*FC))^BETAET, 1) ----
            const float ef_raw = ex2_(fmaf(parBETAET, lg2_(SM3), nBElg2LP));

            // ==== FILL the pow latency: conv + store of PREVIOUS step ====
            {
                const u64   q01 = pack2(pQ0, pQ1);
                const float q2  = pQ2;
                const u64   y01 = fma2(wp[0], q01, A01[0]);
                const float y2  = a2[0] + w[0] * q2;
                #pragma unroll
                for (int j = 0; j < UHL - 2; j++) {
                    A01[j] = fma2(wp[j + 1], q01, A01[j + 1]);
                    a2[j]  = a2[j + 1] + w[j + 1] * q2;
                }
                A01[UHL - 2] = mul2(wp[UHL - 1], q01);
                a2[UHL - 2]  = w[UHL - 1] * q2;
                if (t > 0) {
                    float y0, y1;
                    unpack2(y01, y0, y1);
                    float4 o;
                    o.x = y0 + y1 + y2;
                    o.y = y0;
                    o.z = y1;
                    o.w = y2;
                    out4[(size_t)(t - 1) * NGRID + g] = o;
                }
            }

            // ---- ET and SM update ----
            const float ef = fminf(ef_raw, 1.0f);
            const float ET = fminf(PET * ef, SM3);
            SM = fmaxf(SM3 - ET, NEARZERO);

            // ---- launch next step's soil-wetness pow: min((SM/FC)^BETA, 1) ----
            sw = fminf(ex2_(fmaf(parBETA, lg2_(SM), nBlg2FC)), 1.0f);

            // ==== FILL: response routine (independent of sw, FMA-folded Q0) ====
            float suz = SUZ + recharge + excess;
            const float perc = fminf(suz, parPERC);
            suz -= perc;
            const float Q0 = fmaxf(fmaf(parK0, suz, -k0uzl), 0.0f);
            suz -= Q0;
            const float Q1 = parK1 * suz;
            SUZ = suz - Q1;
            float slz = SLZa + perc;
            const float Q2 = parK2 * slz;
            SLZ = slz - Q2;

            pQ0 = Q0; pQ1 = Q1; pQ2 = Q2;
        }

        __syncwarp();          // all lanes done reading slot pb
        if (k + PIPE < NCHUNK)
            issue_chunk(xphy, k + PIPE, pb, g0, tid, sbase);
        else
            cp_commit();
    }

    // epilogue: conv + store of the final step
    {
        const u64   q01 = pack2(pQ0, pQ1);
        const u64   y01 = fma2(wp[0], q01, A01[0]);
        const float y2  = a2[0] + w[0] * pQ2;
        float y0, y1;
        unpack2(y01, y0, y1);
        float4 o;
        o.x = y0 + y1 + y2;
        o.y = y0;
        o.z = y1;
        o.w = y2;
        out4[(size_t)(NSTEPS - 1) * NGRID + g] = o;
    }
}

extern "C" void kernel_launch(void* const* d_in, const int* in_sizes, int n_in,
                              void* d_out, int out_size) {
    const float* xphy   = (const float*)d_in[0];   // [730, 8000, 3]
    const float* params = (const float*)d_in[1];   // [730, 8000, 16]
    float* out = (float*)d_out;                    // [730, 8000, 4]
    (void)in_sizes; (void)n_in; (void)out_size;

    dim3 block(BT);
    dim3 grid(NGRID / BT);   // 250 warp-private blocks
    hbv_kernel<<<grid, block>>>(xphy, params, out);
}

// round 14
// speedup vs baseline: 2.5674x; 1.0693x over previous
#include <cuda_runtime.h>
#include <cstdint>

#define NSTEPS   730
#define NGRID    8000
#define UHL      15
#define CH       10          // timesteps per smem chunk; 730 = 73 * 10
#define BT       32          // one warp per block, warp-private staging
#define NCHUNK   (NSTEPS / CH)
#define PIPE     4           // cp.async pipeline depth
#define NEARZERO 1e-5f
#define SPLIT    6           // conv taps 0..SPLIT-1 fill snow chain; rest fill pow shadow

__device__ __forceinline__ float ex2_(float x) {
    float r; asm("ex2.approx.ftz.f32 %0, %1;" : "=f"(r) : "f"(x)); return r;
}
__device__ __forceinline__ float lg2_(float x) {
    float r; asm("lg2.approx.ftz.f32 %0, %1;" : "=f"(r) : "f"(x)); return r;
}
__device__ __forceinline__ float sigmoidf_(float x) {
    return 1.0f / (1.0f + __expf(-x));
}

__device__ __forceinline__ uint32_t smem_u32(const void* p) {
    uint32_t a;
    asm("{ .reg .u64 t; cvta.to.shared.u64 t, %1; cvt.u32.u64 %0, t; }" : "=r"(a) : "l"(p));
    return a;
}
__device__ __forceinline__ void cp_async16(uint32_t dst, const void* src) {
    asm volatile("cp.async.ca.shared.global [%0], [%1], 16;\n" :: "r"(dst), "l"(src));
}
__device__ __forceinline__ void cp_commit() { asm volatile("cp.async.commit_group;\n"); }
__device__ __forceinline__ void cp_wait3() { asm volatile("cp.async.wait_group 3;\n"); }

// smem staging: [PIPE buffers][CH steps][BT*3 floats]   (one warp per block)
__shared__ float sbuf[PIPE][CH][BT * 3];

__device__ __forceinline__ void issue_chunk(const float* __restrict__ xphy,
                                            int c, int pb, int g0, int tid,
                                            uint32_t sbase) {
    const int t0 = c * CH;
    constexpr int ROW16 = BT * 3 / 4;        // 24 16B units per row
    constexpr int TOT16 = CH * ROW16;        // 240
    #pragma unroll 1
    for (int idx = tid; idx < TOT16; idx += BT) {
        int row = idx / ROW16;
        int col = idx - row * ROW16;
        const float* src = xphy + ((size_t)(t0 + row) * NGRID + (size_t)g0) * 3 + col * 4;
        uint32_t dst = sbase + (uint32_t)(((pb * CH + row) * (BT * 3) + col * 4) * 4);
        cp_async16(dst, src);
    }
    cp_commit();
}

__global__ __launch_bounds__(BT, 1)
void hbv_kernel(const float* __restrict__ xphy,    // [T, G, 3]
                const float* __restrict__ params,  // [T, G, 16]
                float*       __restrict__ out)     // [T, G, 4]
{
    const int tid = threadIdx.x;
    const int g0  = blockIdx.x * BT;
    const int g   = g0 + tid;
    const uint32_t sbase = smem_u32(&sbuf[0][0][0]);

    // ---------------- static parameters (last timestep only) ----------------
    const float* pr = params + ((size_t)(NSTEPS - 1) * NGRID + (size_t)g) * 16;
    float4 r0 = *(const float4*)(pr + 0);
    float4 r1 = *(const float4*)(pr + 4);
    float4 r2 = *(const float4*)(pr + 8);
    float4 r3 = *(const float4*)(pr + 12);

    const float parBETA   = 1.0f   + sigmoidf_(r0.x) * 5.0f;
    const float parFC     = 50.0f  + sigmoidf_(r0.y) * 950.0f;
    const float parK0     = 0.05f  + sigmoidf_(r0.z) * 0.85f;
    const float parK1     = 0.01f  + sigmoidf_(r0.w) * 0.49f;
    const float parK2     = 0.001f + sigmoidf_(r1.x) * 0.199f;
    const float parLP     = 0.2f   + sigmoidf_(r1.y) * 0.8f;
    const float parPERC   =          sigmoidf_(r1.z) * 10.0f;
    const float parUZL    =          sigmoidf_(r1.w) * 100.0f;
    const float parTT     = -2.5f  + sigmoidf_(r2.x) * 5.0f;
    const float parCFMAX  = 0.5f   + sigmoidf_(r2.y) * 9.5f;
    const float parCFR    =          sigmoidf_(r2.z) * 0.1f;
    const float parCWH    =          sigmoidf_(r2.w) * 0.2f;
    const float parBETAET = 0.3f   + sigmoidf_(r3.x) * 4.7f;
    const float parC      =          sigmoidf_(r3.y);
    const float route_a   =          sigmoidf_(r3.z) * 2.9f;
    const float route_b   =          sigmoidf_(r3.w) * 6.5f;

    const float inv_fc   = __fdividef(1.0f, parFC);
    // pow folding: (x/s)^b = ex2(b*lg2(x) - b*lg2(s))
    const float nBlg2FC  = -parBETA   * lg2_(parFC);
    const float nBElg2LP = -parBETAET * lg2_(parLP * parFC);
    const float k0uzl    = parK0 * parUZL;      // Q0 = max(K0*suz - k0uzl, 0)

    // gamma UH weights; Gamma(a)*theta^a cancels in normalization
    const float aa    = fmaxf(route_a, 0.0f) + 0.1f;
    const float theta = fmaxf(route_b, 0.0f) + 0.5f;
    const float am1   = aa - 1.0f;
    const float invth = __fdividef(1.0f, theta);

    float w[UHL];
    float wsum = 0.0f;
    #pragma unroll
    for (int k = 0; k < UHL; k++) {
        float tk = (float)k + 0.5f;
        float v  = __expf(am1 * __logf(tk) - tk * invth);
        w[k] = v;
        wsum += v;
    }
    const float inv_wsum = __fdividef(1.0f, wsum);
    #pragma unroll
    for (int k = 0; k < UHL; k++) w[k] *= inv_wsum;

    // ---------------- state ----------------
    float SNOWPACK = 0.001f, MELTWATER = 0.001f, SM = 0.001f, SUZ = 0.001f, SLZ = 0.001f;
    float a0[UHL - 1], a1[UHL - 1], a2[UHL - 1];
    #pragma unroll
    for (int j = 0; j < UHL - 1; j++) { a0[j] = 0.0f; a1[j] = 0.0f; a2[j] = 0.0f; }

    // software-pipeline carries: sw for the upcoming step, Qs of previous step
    float sw = fminf(ex2_(fmaf(parBETA, lg2_(SM), nBlg2FC)), 1.0f);
    float pQ0 = 0.0f, pQ1 = 0.0f, pQ2 = 0.0f;   // fictitious step -1 (zeros: exact)

    // prologue: fill 4-deep pipeline
    issue_chunk(xphy, 0, 0, g0, tid, sbase);
    issue_chunk(xphy, 1, 1, g0, tid, sbase);
    issue_chunk(xphy, 2, 2, g0, tid, sbase);
    issue_chunk(xphy, 3, 3, g0, tid, sbase);

    float4* __restrict__ out4 = (float4*)out;
    const int s3 = tid * 3;

    for (int k = 0; k < NCHUNK; k++) {
        const int pb = k & (PIPE - 1);
        cp_wait3();            // chunk k complete (<=3 newer groups in flight)
        __syncwarp();          // publish other lanes' copies within the warp

        #pragma unroll
        for (int u = 0; u < CH; u++) {
            const int t = k * CH + u;
            const float P   = sbuf[pb][u][s3 + 0];
            const float Tt  = sbuf[pb][u][s3 + 1];
            const float PET = sbuf[pb][u][s3 + 2];

            // ---- snow chain (merged melt/refreeze: mutually exclusive by sign) ----
            const float d    = Tt - parTT;
            const float RAIN = (d >= 0.0f) ? P : 0.0f;
            const float SNOW = (d <  0.0f) ? P : 0.0f;
            const float md   = parCFMAX * d;
            const float xr   = fmaxf(md, parCFR * md);   // >=0: melt raw; <0: -refreeze raw
            const float sp0  = SNOWPACK + SNOW;
            const float mw0  = MELTWATER;

            // ==== FILL snow-chain stalls: conv taps 0..SPLIT-1 of PREVIOUS step ====
            const float y0 = a0[0] + w[0] * pQ0;
            const float y1 = a1[0] + w[0] * pQ1;
            const float y2 = a2[0] + w[0] * pQ2;
            #pragma unroll
            for (int j = 0; j < SPLIT; j++) {
                a0[j] = a0[j + 1] + w[j + 1] * pQ0;
                a1[j] = a1[j + 1] + w[j + 1] * pQ1;
                a2[j] = a2[j + 1] + w[j + 1] * pQ2;
            }

            // net snow->melt transfer x = clamp(xr, -mw0, sp0)
            const float x   = fminf(fmaxf(xr, -mw0), sp0);
            const float sp1 = sp0 - x;
            const float mw1 = mw0 + x;
            const float tosoil = fmaxf(fmaf(-parCWH, sp1, mw1), 0.0f);
            MELTWATER = mw1 - tosoil;
            SNOWPACK  = sp1;

            // ---- soil moisture (sw precomputed last iteration) ----
            const float rt   = RAIN + tosoil;
            const float smrt = SM + rt;
            const float recharge = rt * sw;
            const float SM1 = fmaf(-rt, sw, smrt);
            const float excess = fmaxf(SM1 - parFC, 0.0f);
            const float SM2 = fminf(SM1, parFC);
            // capillary (min-with-SLZ redundant: C<=1 and SM2<=FC)
            const float cSLZ = parC * SLZ;
            const float cap  = cSLZ * fmaf(-inv_fc, SM2, 1.0f);
            const float SM3  = fmaxf(SM2 + cap, NEARZERO);
            const float SLZa = fmaxf(SLZ - cap, NEARZERO);

            // ---- launch evapfactor pow: min((SM3/(LP*FC))^BETAET, 1) ----
            const float ef_raw = ex2_(fmaf(parBETAET, lg2_(SM3), nBElg2LP));

            // ==== FILL the pow latency: conv taps SPLIT..end of PREVIOUS step ====
            #pragma unroll
            for (int j = SPLIT; j < UHL - 2; j++) {
                a0[j] = a0[j + 1] + w[j + 1] * pQ0;
                a1[j] = a1[j + 1] + w[j + 1] * pQ1;
                a2[j] = a2[j + 1] + w[j + 1] * pQ2;
            }
            a0[UHL - 2] = w[UHL - 1] * pQ0;
            a1[UHL - 2] = w[UHL - 1] * pQ1;
            a2[UHL - 2] = w[UHL - 1] * pQ2;

            // ---- ET and SM update ----
            const float ef = fminf(ef_raw, 1.0f);
            const float ET = fminf(PET * ef, SM3);
            SM = fmaxf(SM3 - ET, NEARZERO);

            // ---- launch next step's soil-wetness pow: min((SM/FC)^BETA, 1) ----
            sw = fminf(ex2_(fmaf(parBETA, lg2_(SM), nBlg2FC)), 1.0f);

            // ==== FILL: store of previous step's routed output ====
            if (t > 0) {
                float4 o;
                o.x = y0 + y1 + y2;
                o.y = y0;
                o.z = y1;
                o.w = y2;
                out4[(size_t)(t - 1) * NGRID + g] = o;
            }

            // ==== FILL: response routine (independent of sw) ====
            float suz = SUZ + recharge + excess;
            const float perc = fminf(suz, parPERC);
            suz -= perc;
            const float Q0 = fmaxf(fmaf(parK0, suz, -k0uzl), 0.0f);
            suz -= Q0;
            const float Q1 = parK1 * suz;
            SUZ = suz - Q1;
            float slz = SLZa + perc;
            const float Q2 = parK2 * slz;
            SLZ = slz - Q2;

            pQ0 = Q0; pQ1 = Q1; pQ2 = Q2;
        }

        __syncwarp();          // all lanes done reading slot pb
        if (k + PIPE < NCHUNK)
            issue_chunk(xphy, k + PIPE, pb, g0, tid, sbase);
        else
            cp_commit();
    }

    // epilogue: conv + store of the final step
    {
        const float y0 = a0[0] + w[0] * pQ0;
        const float y1 = a1[0] + w[0] * pQ1;
        const float y2 = a2[0] + w[0] * pQ2;
        float4 o;
        o.x = y0 + y1 + y2;
        o.y = y0;
        o.z = y1;
        o.w = y2;
        out4[(size_t)(NSTEPS - 1) * NGRID + g] = o;
    }
}

extern "C" void kernel_launch(void* const* d_in, const int* in_sizes, int n_in,
                              void* d_out, int out_size) {
    const float* xphy   = (const float*)d_in[0];   // [730, 8000, 3]
    const float* params = (const float*)d_in[1];   // [730, 8000, 16]
    float* out = (float*)d_out;                    // [730, 8000, 4]
    (void)in_sizes; (void)n_in; (void)out_size;

    dim3 block(BT);
    dim3 grid(NGRID / BT);   // 250 warp-private blocks
    hbv_kernel<<<grid, block>>>(xphy, params, out);
}

// round 15
// speedup vs baseline: 3.0039x; 1.1700x over previous
#include <cuda_runtime.h>
#include <cstdint>

#define NSTEPS   730
#define NGRID    8000
#define UHL      15
#define CH       10          // timesteps per chunk; 730 = 73 * 10
#define NCHUNK   (NSTEPS / CH)
#define PIPE     2           // cp.async pipeline depth (slot = chunk & 1)
#define PBT      64          // producer threads (2 warps) = cells per block
#define BT       128         // block: warps 0,1 produce; warps 2,3 route
#define NEARZERO 1e-5f

__device__ __forceinline__ float ex2_(float x) {
    float r; asm("ex2.approx.ftz.f32 %0, %1;" : "=f"(r) : "f"(x)); return r;
}
__device__ __forceinline__ float lg2_(float x) {
    float r; asm("lg2.approx.ftz.f32 %0, %1;" : "=f"(r) : "f"(x)); return r;
}
__device__ __forceinline__ float sigmoidf_(float x) {
    return 1.0f / (1.0f + __expf(-x));
}

__device__ __forceinline__ uint32_t smem_u32(const void* p) {
    uint32_t a;
    asm("{ .reg .u64 t; cvta.to.shared.u64 t, %1; cvt.u32.u64 %0, t; }" : "=r"(a) : "l"(p));
    return a;
}
__device__ __forceinline__ void cp_async16(uint32_t dst, const void* src) {
    asm volatile("cp.async.ca.shared.global [%0], [%1], 16;\n" :: "r"(dst), "l"(src));
}
__device__ __forceinline__ void cp_commit() { asm volatile("cp.async.commit_group;\n"); }
__device__ __forceinline__ void cp_wait1() { asm volatile("cp.async.wait_group 1;\n"); }

// input staging (producers): [PIPE][CH][PBT*3] = 15 KB
__shared__ float sbuf[PIPE][CH][PBT * 3];
// Q handoff ring (producer -> router): [2][CH][PBT*3] = 15 KB
__shared__ float qring[2][CH][PBT * 3];

// cooperative over the 64 producer threads (tid 0..63)
__device__ __forceinline__ void issue_chunk(const float* __restrict__ xphy,
                                            int c, int g0, int tid,
                                            uint32_t sbase) {
    const int t0 = c * CH;
    const int pb = c & 1;
    constexpr int ROW16 = PBT * 3 / 4;       // 48 16B units per row
    constexpr int TOT16 = CH * ROW16;        // 480
    #pragma unroll 1
    for (int idx = tid; idx < TOT16; idx += PBT) {
        int row = idx / ROW16;
        int col = idx - row * ROW16;
        const float* src = xphy + ((size_t)(t0 + row) * NGRID + (size_t)g0) * 3 + col * 4;
        uint32_t dst = sbase + (uint32_t)(((pb * CH + row) * (PBT * 3) + col * 4) * 4);
        cp_async16(dst, src);
    }
    cp_commit();
}

__global__ __launch_bounds__(BT, 1)
void hbv_kernel(const float* __restrict__ xphy,    // [T, G, 3]
                const float* __restrict__ params,  // [T, G, 16]
                float*       __restrict__ out)     // [T, G, 4]
{
    const int tid  = threadIdx.x;
    const int wid  = tid >> 5;
    const int lane = tid & 31;
    const int g0   = blockIdx.x * PBT;
    const bool producer = (wid < 2);
    const int cidx = (producer ? wid : (wid - 2)) * 32 + lane;   // 0..63
    const int g    = g0 + cidx;
    const int c3   = cidx * 3;
    const uint32_t sbase = smem_u32(&sbuf[0][0][0]);

    const float* pr = params + ((size_t)(NSTEPS - 1) * NGRID + (size_t)g) * 16;

    if (producer) {
        // ================= PRODUCER: serial HBV recurrence =================
        float4 r0 = *(const float4*)(pr + 0);
        float4 r1 = *(const float4*)(pr + 4);
        float4 r2 = *(const float4*)(pr + 8);
        float4 r3 = *(const float4*)(pr + 12);

        const float parBETA   = 1.0f   + sigmoidf_(r0.x) * 5.0f;
        const float parFC     = 50.0f  + sigmoidf_(r0.y) * 950.0f;
        const float parK0     = 0.05f  + sigmoidf_(r0.z) * 0.85f;
        const float parK1     = 0.01f  + sigmoidf_(r0.w) * 0.49f;
        const float parK2     = 0.001f + sigmoidf_(r1.x) * 0.199f;
        const float parLP     = 0.2f   + sigmoidf_(r1.y) * 0.8f;
        const float parPERC   =          sigmoidf_(r1.z) * 10.0f;
        const float parUZL    =          sigmoidf_(r1.w) * 100.0f;
        const float parTT     = -2.5f  + sigmoidf_(r2.x) * 5.0f;
        const float parCFMAX  = 0.5f   + sigmoidf_(r2.y) * 9.5f;
        const float parCFR    =          sigmoidf_(r2.z) * 0.1f;
        const float parCWH    =          sigmoidf_(r2.w) * 0.2f;
        const float parBETAET = 0.3f   + sigmoidf_(r3.x) * 4.7f;
        const float parC      =          sigmoidf_(r3.y);

        const float inv_fc   = __fdividef(1.0f, parFC);
        const float nBlg2FC  = -parBETA   * lg2_(parFC);
        const float nBElg2LP = -parBETAET * lg2_(parLP * parFC);
        const float k0uzl    = parK0 * parUZL;

        float SNOWPACK = 0.001f, MELTWATER = 0.001f, SM = 0.001f, SUZ = 0.001f, SLZ = 0.001f;
        float sw = fminf(ex2_(fmaf(parBETA, lg2_(SM), nBlg2FC)), 1.0f);
        float pQ0 = 0.0f, pQ1 = 0.0f, pQ2 = 0.0f;

        issue_chunk(xphy, 0, g0, tid, sbase);
        issue_chunk(xphy, 1, g0, tid, sbase);

        for (int k = 0; k <= NCHUNK; k++) {
            if (k < NCHUNK) cp_wait1();
            __syncthreads();   // staging visible across producer warps; ring handoff
            if (k >= NCHUNK) break;   // last iteration: router still works

            const int pb = k & 1;
            const int qb = k & 1;

            #pragma unroll
            for (int u = 0; u < CH; u++) {
                const float P   = sbuf[pb][u][c3 + 0];
                const float Tt  = sbuf[pb][u][c3 + 1];
                const float PET = sbuf[pb][u][c3 + 2];

                // ---- snow chain (merged melt/refreeze) ----
                const float d    = Tt - parTT;
                const float RAIN = (d >= 0.0f) ? P : 0.0f;
                const float SNOW = (d <  0.0f) ? P : 0.0f;
                const float md   = parCFMAX * d;
                const float xr   = fmaxf(md, parCFR * md);
                const float sp0  = SNOWPACK + SNOW;
                const float mw0  = MELTWATER;
                const float x    = fminf(fmaxf(xr, -mw0), sp0);
                const float sp1  = sp0 - x;
                const float mw1  = mw0 + x;
                const float tosoil = fmaxf(fmaf(-parCWH, sp1, mw1), 0.0f);
                MELTWATER = mw1 - tosoil;
                SNOWPACK  = sp1;

                // ---- soil moisture (sw from previous iteration) ----
                const float rt   = RAIN + tosoil;
                const float smrt = SM + rt;
                const float recharge = rt * sw;
                const float SM1 = fmaf(-rt, sw, smrt);
                const float excess = fmaxf(SM1 - parFC, 0.0f);
                const float SM2 = fminf(SM1, parFC);
                const float cSLZ = parC * SLZ;
                const float cap  = cSLZ * fmaf(-inv_fc, SM2, 1.0f);
                const float SM3  = fmaxf(SM2 + cap, NEARZERO);
                const float SLZa = fmaxf(SLZ - cap, NEARZERO);

                // ---- launch evapfactor pow ----
                const float ef_raw = ex2_(fmaf(parBETAET, lg2_(SM3), nBElg2LP));

                // ==== FILL pow shadow: publish PREVIOUS step's Qs ====
                if (u > 0) {   // compile-time in unrolled body
                    qring[qb][u - 1][c3 + 0] = pQ0;
                    qring[qb][u - 1][c3 + 1] = pQ1;
                    qring[qb][u - 1][c3 + 2] = pQ2;
                }

                // ---- ET & SM  (min(ET,SM3) folds into the outer max) ----
                const float ef = fminf(ef_raw, 1.0f);
                SM = fmaxf(fmaf(-PET, ef, SM3), NEARZERO);

                // ---- next step's soil-wetness pow ----
                sw = fminf(ex2_(fmaf(parBETA, lg2_(SM), nBlg2FC)), 1.0f);

                // ==== FILL: response routine (independent of sw) ====
                float suz = SUZ + recharge + excess;
                const float perc = fminf(suz, parPERC);
                suz -= perc;
                const float Q0 = fmaxf(fmaf(parK0, suz, -k0uzl), 0.0f);
                suz -= Q0;
                const float Q1 = parK1 * suz;
                SUZ = suz - Q1;
                float slz = SLZa + perc;
                const float Q2 = parK2 * slz;
                SLZ = slz - Q2;

                pQ0 = Q0; pQ1 = Q1; pQ2 = Q2;
            }
            // flush final step of this chunk into the ring
            qring[qb][CH - 1][c3 + 0] = pQ0;
            qring[qb][CH - 1][c3 + 1] = pQ1;
            qring[qb][CH - 1][c3 + 2] = pQ2;

            if (k + PIPE < NCHUNK)
                issue_chunk(xphy, k + PIPE, g0, tid, sbase);
            else
                cp_commit();   // empty group keeps wait_group accounting correct
        }
    } else {
        // ================= ROUTER: 15-tap UH convolution =================
        float4 r3 = *(const float4*)(pr + 12);
        const float route_a = sigmoidf_(r3.z) * 2.9f;
        const float route_b = sigmoidf_(r3.w) * 6.5f;
        const float aa    = fmaxf(route_a, 0.0f) + 0.1f;
        const float theta = fmaxf(route_b, 0.0f) + 0.5f;
        const float am1   = aa - 1.0f;
        const float invth = __fdividef(1.0f, theta);

        float w[UHL];
        float wsum = 0.0f;
        #pragma unroll
        for (int k = 0; k < UHL; k++) {
            float tk = (float)k + 0.5f;
            float v  = __expf(am1 * __logf(tk) - tk * invth);
            w[k] = v;
            wsum += v;
        }
        const float inv_wsum = __fdividef(1.0f, wsum);
        #pragma unroll
        for (int k = 0; k < UHL; k++) w[k] *= inv_wsum;

        float a0[UHL - 1], a1[UHL - 1], a2[UHL - 1];
        #pragma unroll
        for (int j = 0; j < UHL - 1; j++) { a0[j] = 0.0f; a1[j] = 0.0f; a2[j] = 0.0f; }

        float4* __restrict__ out4 = (float4*)out;

        for (int k = 0; k <= NCHUNK; k++) {
            __syncthreads();   // producers' chunk k-1 ring writes now visible
            if (k < 1) continue;

            const int qb = (k - 1) & 1;
            const int t0 = (k - 1) * CH;

            #pragma unroll
            for (int u = 0; u < CH; u++) {
                const float q0 = qring[qb][u][c3 + 0];
                const float q1 = qring[qb][u][c3 + 1];
                const float q2 = qring[qb][u][c3 + 2];

                const float y0 = a0[0] + w[0] * q0;
                const float y1 = a1[0] + w[0] * q1;
                const float y2 = a2[0] + w[0] * q2;
                #pragma unroll
                for (int j = 0; j < UHL - 2; j++) {
                    a0[j] = a0[j + 1] + w[j + 1] * q0;
                    a1[j] = a1[j + 1] + w[j + 1] * q1;
                    a2[j] = a2[j + 1] + w[j + 1] * q2;
                }
                a0[UHL - 2] = w[UHL - 1] * q0;
                a1[UHL - 2] = w[UHL - 1] * q1;
                a2[UHL - 2] = w[UHL - 1] * q2;

                float4 o;
                o.x = y0 + y1 + y2;
                o.y = y0;
                o.z = y1;
                o.w = y2;
                out4[(size_t)(t0 + u) * NGRID + g] = o;
            }
        }
    }
}

extern "C" void kernel_launch(void* const* d_in, const int* in_sizes, int n_in,
                              void* d_out, int out_size) {
    const float* xphy   = (const float*)d_in[0];   // [730, 8000, 3]
    const float* params = (const float*)d_in[1];   // [730, 8000, 16]
    float* out = (float*)d_out;                    // [730, 8000, 4]
    (void)in_sizes; (void)n_in; (void)out_size;

    dim3 block(BT);
    dim3 grid(NGRID / PBT);   // 125 blocks: 1 per SM, 4 warps on 4 SMSPs
    hbv_kernel<<<grid, block>>>(xphy, params, out);
}